// round 9
// baseline (speedup 1.0000x reference)
#include <cuda_runtime.h>
#include <cstdint>

// LinearTPReadOut: out[n] = w_tp/sqrt(3) * (1/128) * sum_i A_i(n)*B_i(n)
//   A_i(n) = sum_u x[n, 128+3u+i] * w_lin[u,0],  B_i with w_lin[u,1]
// x: (N,1152) f32, w_lin: (128,2) f32, w_tp: (1,) f32, out: (N,) f32
//
// Warp-local 3-deep cp.async pipeline. Warp w of a block owns rows
// {blockRow + w + 8t, t=0..TILES-1} and a private 3-slot smem ring
// (96 float4 per slot). Per tile: wait_group + syncwarp (NO block barriers),
// prefetch tile t+2 into the free slot BEFORE computing tile t -> each warp
// keeps ~2 tiles (3KB) of loads in flight continuously = steady DRAM demand.
// Loads: lane stores f4 {lane, lane+32, lane+64} -> 3x 512B-dense cp.async.cg
// (bypasses L1, perfect sectors). Compute: R6's per-lane u-aligned mapping
// (lane l owns u=4l..4l+3, 12 floats at 48B stride from smem; conflict-free:
// 8-lane LDS.128 phase covers all 32 banks). Weights: 8 regs/lane.
// Reduction: butterfly all-reduce B (15 shfl) + per-lane dot + reduce (5).

#define ROW_STRIDE_F 1152
#define COL_OFF      128
#define TILES        4      // rows per warp; 32 rows per block
#define NBUF         3

__global__ __launch_bounds__(256)
void lintp_kernel(const float* __restrict__ x,
                  const float* __restrict__ w_lin,
                  const float* __restrict__ w_tp,
                  float* __restrict__ out, int n)
{
    __shared__ float4 buf[8][NBUF][96];   // per-warp 3-slot ring

    const int tid  = threadIdx.x;
    const int lane = tid & 31;
    const int warp = tid >> 5;

    // per-lane weights (u = 4l..4l+3): 8 registers
    const float4* wp = reinterpret_cast<const float4*>(w_lin) + 2 * lane;
    const float4 wA = __ldg(wp);      // w0[4l], w1[4l], w0[4l+1], w1[4l+1]
    const float4 wB = __ldg(wp + 1);  // w0[4l+2], w1[4l+2], w0[4l+3], w1[4l+3]
    const float scale = __ldg(w_tp) * 0.57735026918962576451f * (1.0f / 128.0f);

    const int rowStart = blockIdx.x * (8 * TILES) + warp;   // rows stride 8
    const uint32_t sbase =
        (uint32_t)__cvta_generic_to_shared(&buf[warp][0][0]);

    // ---- issue one tile's loads (3 dense 512B cp.async.cg) + commit ----
    #define LOAD_TILE(T, H)                                                   \
        do {                                                                  \
            const int row_  = rowStart + 8 * (T);                             \
            const int rowc_ = row_ < n ? row_ : n - 1;                        \
            const float4* gp_ = reinterpret_cast<const float4*>(              \
                x + (size_t)rowc_ * ROW_STRIDE_F + COL_OFF) + lane;           \
            const uint32_t dst_ = sbase + (H) * 1536u + (uint32_t)lane * 16u; \
            asm volatile("cp.async.cg.shared.global [%0], [%1], 16;"          \
                         :: "r"(dst_), "l"(gp_));                             \
            asm volatile("cp.async.cg.shared.global [%0], [%1], 16;"          \
                         :: "r"(dst_ + 512u), "l"(gp_ + 32));                 \
            asm volatile("cp.async.cg.shared.global [%0], [%1], 16;"          \
                         :: "r"(dst_ + 1024u), "l"(gp_ + 64));                \
            asm volatile("cp.async.commit_group;");                          \
        } while (0)

    LOAD_TILE(0, 0);
    LOAD_TILE(1, 1);

    #pragma unroll
    for (int t = 0; t < TILES; t++) {
        const int h = t % NBUF;

        // wait until tile t's group is done (2 outstanding -> allow 1;
        // last iteration has only 1 outstanding -> require 0)
        if (t < TILES - 1)
            asm volatile("cp.async.wait_group 1;");
        else
            asm volatile("cp.async.wait_group 0;");
        __syncwarp();   // cross-lane smem visibility within the warp

        // prefetch t+2 into the free slot BEFORE computing t
        if (t + 2 < TILES)
            LOAD_TILE(t + 2, (t + 2) % NBUF);

        // ---- compute tile t (R6 math) ----
        const float4* tp = &buf[warp][h][3 * lane];
        const float4 v0 = tp[0];
        const float4 v1 = tp[1];
        const float4 v2 = tp[2];

        //  v0 = {u0i0, u0i1, u0i2, u1i0}
        //  v1 = {u1i1, u1i2, u2i0, u2i1}
        //  v2 = {u2i2, u3i0, u3i1, u3i2}
        const float A0 = v0.x*wA.x + v0.w*wA.z + v1.z*wB.x + v2.y*wB.z;
        const float A1 = v0.y*wA.x + v1.x*wA.z + v1.w*wB.x + v2.z*wB.z;
        const float A2 = v0.z*wA.x + v1.y*wA.z + v2.x*wB.x + v2.w*wB.z;
        float B0 = v0.x*wA.y + v0.w*wA.w + v1.z*wB.y + v2.y*wB.w;
        float B1 = v0.y*wA.y + v1.x*wA.w + v1.w*wB.y + v2.z*wB.w;
        float B2 = v0.z*wA.y + v1.y*wA.w + v2.x*wB.y + v2.w*wB.w;

        #pragma unroll
        for (int m = 16; m > 0; m >>= 1) {
            B0 += __shfl_xor_sync(0xffffffffu, B0, m);
            B1 += __shfl_xor_sync(0xffffffffu, B1, m);
            B2 += __shfl_xor_sync(0xffffffffu, B2, m);
        }

        float p = A0 * B0;
        p = fmaf(A1, B1, p);
        p = fmaf(A2, B2, p);

        #pragma unroll
        for (int m = 16; m > 0; m >>= 1)
            p += __shfl_down_sync(0xffffffffu, p, m);

        const int row = rowStart + 8 * t;
        if (lane == 0 && row < n)
            out[row] = scale * p;
    }
    #undef LOAD_TILE
}

extern "C" void kernel_launch(void* const* d_in, const int* in_sizes, int n_in,
                              void* d_out, int out_size)
{
    const float* x     = (const float*)d_in[0];
    const float* w_lin = (const float*)d_in[1];
    const float* w_tp  = (const float*)d_in[2];
    float* out = (float*)d_out;

    const int n = in_sizes[0] / ROW_STRIDE_F;            // 200000
    const int rowsPerBlock = 8 * TILES;                  // 32
    const int blocks = (n + rowsPerBlock - 1) / rowsPerBlock;   // 6250
    lintp_kernel<<<blocks, 256>>>(x, w_lin, w_tp, out, n);
}